// round 13
// baseline (speedup 1.0000x reference)
#include <cuda_runtime.h>
#include <cuda_fp16.h>
#include <math.h>

#define N_CAMS 5
#define Bn 4
#define Jn 15
#define Hn 128
#define Wn 240
#define CX 80
#define CY 80
#define CZ 20
#define NBINS (CX*CY*CZ)        // 128000
#define HW (Hn*Wn)              // 30720
#define NB (N_CAMS*Bn)          // 20 planes
#define THREADS 256
#define BLOCKS_PER_B (NBINS/THREADS)  // 500
#define EPSV 1e-6f

// Joint-chunked fp16 heatmaps:
//   record per (cam,b,chunk,pixel) = 8 halves (chunk0: joints 0-7, chunk1: joints 8-14 + pad) = 16B.
// Layout: [nb][chunk][pixel][8]
__device__ __align__(16) __half g_packT[(size_t)NB * 2 * HW * 8 + 64];   // ~19.7 MB

__global__ __launch_bounds__(256) void pack_kernel(const float* __restrict__ heat) {
    const int i = blockIdx.x * 256 + threadIdx.x;     // < NB*HW
    const int nb = i / HW;
    const int r  = i - nb * HW;
    const float* hp = heat + ((size_t)nb * Jn) * HW + r;
    __align__(16) __half tmp[16];
    #pragma unroll
    for (int j = 0; j < Jn; j++)
        tmp[j] = __float2half_rn(hp[(size_t)j * HW]);   // coalesced across warp per j
    tmp[15] = __float2half_rn(0.0f);
    const uint4* src = reinterpret_cast<const uint4*>(tmp);
    uint4* dst0 = reinterpret_cast<uint4*>(g_packT + (((size_t)nb * 2      ) * HW + r) * 8);
    uint4* dst1 = reinterpret_cast<uint4*>(g_packT + (((size_t)nb * 2 + 1U ) * HW + r) * 8);
    *dst0 = src[0];
    *dst1 = src[1];
}

__global__ __launch_bounds__(THREADS, 5) void project_kernel(
    const float* __restrict__ Rm,     // (5,4,3,3)
    const float* __restrict__ Tm,     // (5,4,3)
    const float* __restrict__ fm,     // (5,4,2)
    const float* __restrict__ cm,     // (5,4,2)
    const float* __restrict__ km,     // (5,4,3)
    const float* __restrict__ pm,     // (5,4,2)
    const float* __restrict__ whm,    // (5,4,2)
    const float* __restrict__ gc,     // (4,3)
    const float* __restrict__ gs,     // (3,)
    float* __restrict__ cubes,        // (4,15,128000)
    float* __restrict__ grids)        // (4,128000,3)
{
    __shared__ float s[N_CAMS * 23];

    const int b = blockIdx.x / BLOCKS_PER_B;
    const int m = (blockIdx.x % BLOCKS_PER_B) * THREADS + threadIdx.x;

    // Stage camera params for this batch into shared: per cam 23 floats:
    // R[0..8], T[9..11], f[12..13], c[14..15], k[16..18], p[19..20], wh[21..22]
    for (int i = threadIdx.x; i < N_CAMS * 23; i += THREADS) {
        const int n = i / 23, q = i % 23;
        const int nb = n * Bn + b;
        float v;
        if      (q < 9)  v = Rm [nb*9 + q];
        else if (q < 12) v = Tm [nb*3 + (q-9)];
        else if (q < 14) v = fm [nb*2 + (q-12)];
        else if (q < 16) v = cm [nb*2 + (q-14)];
        else if (q < 19) v = km [nb*3 + (q-16)];
        else if (q < 21) v = pm [nb*2 + (q-19)];
        else             v = whm[nb*2 + (q-21)];
        s[i] = v;
    }
    __syncthreads();

    // Voxel coordinates: m = (ix*CY + iy)*CZ + iz
    const int ixg = m / (CY * CZ);
    const int iyg = (m / CZ) % CY;
    const int izg = m % CZ;
    const float gs0 = gs[0], gs1 = gs[1], gs2 = gs[2];
    const float gx = -0.5f*gs0 + (float)ixg * (gs0 / (float)(CX-1)) + gc[b*3+0];
    const float gy = -0.5f*gs1 + (float)iyg * (gs1 / (float)(CY-1)) + gc[b*3+1];
    const float gz = -0.5f*gs2 + (float)izg * (gs2 / (float)(CZ-1)) + gc[b*3+2];

    grids[((long)b*NBINS + m)*3 + 0] = gx;
    grids[((long)b*NBINS + m)*3 + 1] = gy;
    grids[((long)b*NBINS + m)*3 + 2] = gz;

    float den = EPSV;
    float2 acc2[8];
    #pragma unroll
    for (int jj = 0; jj < 8; jj++) acc2[jj] = make_float2(0.f, 0.f);

    #pragma unroll
    for (int n = 0; n < N_CAMS; n++) {
        const float* cp = s + n*23;
        const float dx = gx - cp[9], dy = gy - cp[10], dz = gz - cp[11];
        const float xc0 = cp[0]*dx + cp[1]*dy + cp[2]*dz;
        const float xc1 = cp[3]*dx + cp[4]*dy + cp[5]*dz;
        const float xc2 = cp[6]*dx + cp[7]*dy + cp[8]*dz;
        const float inv = 1.0f / xc2;
        const float y0 = xc0 * inv, y1 = xc1 * inv;
        const float r2 = y0*y0 + y1*y1;
        const float radial = 1.0f + cp[16]*r2 + cp[17]*r2*r2 + cp[18]*r2*r2*r2;
        const float tanp = cp[19]*y1 + cp[20]*y0;
        const float rt = radial + tanp;
        const float xy0 = y0*rt + r2*cp[20];
        const float xy1 = y1*rt + r2*cp[19];
        const float px = xy0*cp[12] + cp[14];
        const float py = xy1*cp[13] + cp[15];
        const float wv = cp[21], hv = cp[22];
        const float bound = (px >= 0.0f && py >= 0.0f && px < wv && py < hv) ? 1.0f : 0.0f;
        den += bound;
        const float mwh = fmaxf(wv, hv);
        float pxc = fminf(fmaxf(px, -1.0f), mwh);
        float pyc = fminf(fmaxf(py, -1.0f), mwh);
        float nx = pxc / (wv - 1.0f) * 2.0f - 1.0f;
        float ny = pyc / (hv - 1.0f) * 2.0f - 1.0f;
        nx = fminf(fmaxf(nx, -1.1f), 1.1f);
        ny = fminf(fmaxf(ny, -1.1f), 1.1f);
        const float fx = (nx + 1.0f) * 0.5f * (float)(Wn - 1);
        const float fy = (ny + 1.0f) * 0.5f * (float)(Hn - 1);
        const float x0f = floorf(fx), y0f = floorf(fy);
        const float wx1 = fx - x0f, wx0 = 1.0f - wx1;
        const float wy1 = fy - y0f, wy0 = 1.0f - wy1;
        const int x0i = (int)x0f;
        const int y0i = (int)y0f;
        // Map logical corner weights onto the fetched 2x2 slots (base clamped to [0,W-2]/[0,H-2]).
        // Under bound=1: x0i in [0,W-1], y0i in [0,H-1]. x0i==W-1 => x0 value sits in slot B; x1 invalid.
        const bool xe = (x0i >= Wn-1);
        const bool ye = (y0i >= Hn-1);
        const int xb = min(max(x0i, 0), Wn-2);
        const int yb = min(max(y0i, 0), Hn-2);
        const float wxA = xe ? 0.0f : wx0;
        const float wxB = xe ? wx0  : wx1;
        const float wyA = ye ? 0.0f : wy0;
        const float wyB = ye ? wy0  : wy1;
        const float w00 = wxA*wyA*bound;
        const float w01 = wxB*wyA*bound;
        const float w10 = wxA*wyB*bound;
        const float w11 = wxB*wyB*bound;

        const size_t pixoff = (size_t)yb*Wn + xb;
        const size_t base0 = ((size_t)(n*Bn + b) * 2 * HW + pixoff) * 8;        // chunk0, halves
        const size_t base1 = base0 + (size_t)HW * 8;                            // chunk1

        #pragma unroll
        for (int c = 0; c < 2; c++) {
            const size_t p = c ? base1 : base0;
            const uint4* q0 = reinterpret_cast<const uint4*>(g_packT + p);                    // row yb
            const uint4* q1 = reinterpret_cast<const uint4*>(g_packT + p + (size_t)Wn*8);     // row yb+1
            const uint4 r00 = __ldg(q0);       // pixel (yb,  xb)
            const uint4 r01 = __ldg(q0 + 1);   // pixel (yb,  xb+1)
            const uint4 r10 = __ldg(q1);       // pixel (yb+1,xb)
            const uint4 r11 = __ldg(q1 + 1);   // pixel (yb+1,xb+1)
            const unsigned int* c00 = &r00.x;
            const unsigned int* c01 = &r01.x;
            const unsigned int* c10 = &r10.x;
            const unsigned int* c11 = &r11.x;
            #pragma unroll
            for (int t = 0; t < 4; t++) {
                const int jj = c*4 + t;
                const float2 v00 = __half22float2(*reinterpret_cast<const __half2*>(&c00[t]));
                const float2 v01 = __half22float2(*reinterpret_cast<const __half2*>(&c01[t]));
                const float2 v10 = __half22float2(*reinterpret_cast<const __half2*>(&c10[t]));
                const float2 v11 = __half22float2(*reinterpret_cast<const __half2*>(&c11[t]));
                acc2[jj].x += w00*v00.x + w01*v01.x + w10*v10.x + w11*v11.x;
                acc2[jj].y += w00*v00.y + w01*v01.y + w10*v10.y + w11*v11.y;
            }
        }
    }

    const float invden = 1.0f / den;

    #pragma unroll
    for (int j = 0; j < Jn; j++) {
        const float a = (j & 1) ? acc2[j>>1].y : acc2[j>>1].x;
        float v = a * invden;
        v = fminf(fmaxf(v, 0.0f), 1.0f);
        cubes[((long)b*Jn + j)*NBINS + m] = v;
    }
}

extern "C" void kernel_launch(void* const* d_in, const int* in_sizes, int n_in,
                              void* d_out, int out_size) {
    const float* heat = (const float*)d_in[0];
    const float* Rm   = (const float*)d_in[1];
    const float* Tm   = (const float*)d_in[2];
    const float* fm   = (const float*)d_in[3];
    const float* cm   = (const float*)d_in[4];
    const float* km   = (const float*)d_in[5];
    const float* pm   = (const float*)d_in[6];
    const float* whm  = (const float*)d_in[7];
    const float* gc   = (const float*)d_in[8];
    const float* gs   = (const float*)d_in[9];

    float* cubes = (float*)d_out;
    float* grids = cubes + (long)Bn * Jn * NBINS;   // tuple output: cubes then grids

    pack_kernel<<<(NB * HW) / 256, 256>>>(heat);
    project_kernel<<<Bn * BLOCKS_PER_B, THREADS>>>(Rm, Tm, fm, cm, km, pm, whm, gc, gs,
                                                   cubes, grids);
}

// round 14
// speedup vs baseline: 1.1039x; 1.1039x over previous
#include <cuda_runtime.h>
#include <cuda_fp16.h>
#include <math.h>

#define N_CAMS 5
#define Bn 4
#define Jn 15
#define Hn 128
#define Wn 240
#define CX 80
#define CY 80
#define CZ 20
#define NBINS (CX*CY*CZ)        // 128000
#define HW (Hn*Wn)              // 30720
#define NB (N_CAMS*Bn)          // 20 planes
#define THREADS 256
#define BLOCKS_PER_B (NBINS/THREADS)  // 500
#define EPSV 1e-6f

// Joint-chunked fp16 heatmaps:
//   record per (cam,b,chunk,pixel) = 8 halves (chunk0: joints 0-7, chunk1: joints 8-14 + pad) = 16B.
// Layout: [nb][chunk][pixel][8]
__device__ __align__(16) __half g_packT[(size_t)NB * 2 * HW * 8 + 64];   // ~19.7 MB

__global__ __launch_bounds__(256) void pack_kernel(const float* __restrict__ heat) {
    const int i = blockIdx.x * 256 + threadIdx.x;     // < NB*HW
    const int nb = i / HW;
    const int r  = i - nb * HW;
    const float* hp = heat + ((size_t)nb * Jn) * HW + r;
    __align__(16) __half tmp[16];
    #pragma unroll
    for (int j = 0; j < Jn; j++)
        tmp[j] = __float2half_rn(hp[(size_t)j * HW]);   // coalesced across warp per j
    tmp[15] = __float2half_rn(0.0f);
    const uint4* src = reinterpret_cast<const uint4*>(tmp);
    uint4* dst0 = reinterpret_cast<uint4*>(g_packT + (((size_t)nb * 2      ) * HW + r) * 8);
    uint4* dst1 = reinterpret_cast<uint4*>(g_packT + (((size_t)nb * 2 + 1U ) * HW + r) * 8);
    *dst0 = src[0];
    *dst1 = src[1];
}

__global__ __launch_bounds__(THREADS) void project_kernel(
    const float* __restrict__ Rm,     // (5,4,3,3)
    const float* __restrict__ Tm,     // (5,4,3)
    const float* __restrict__ fm,     // (5,4,2)
    const float* __restrict__ cm,     // (5,4,2)
    const float* __restrict__ km,     // (5,4,3)
    const float* __restrict__ pm,     // (5,4,2)
    const float* __restrict__ whm,    // (5,4,2)
    const float* __restrict__ gc,     // (4,3)
    const float* __restrict__ gs,     // (3,)
    float* __restrict__ cubes,        // (4,15,128000)
    float* __restrict__ grids)        // (4,128000,3)
{
    __shared__ float s[N_CAMS * 23];

    const int b = blockIdx.x / BLOCKS_PER_B;
    const int m = (blockIdx.x % BLOCKS_PER_B) * THREADS + threadIdx.x;

    // Stage camera params for this batch into shared: per cam 23 floats:
    // R[0..8], T[9..11], f[12..13], c[14..15], k[16..18], p[19..20], wh[21..22]
    for (int i = threadIdx.x; i < N_CAMS * 23; i += THREADS) {
        const int n = i / 23, q = i % 23;
        const int nb = n * Bn + b;
        float v;
        if      (q < 9)  v = Rm [nb*9 + q];
        else if (q < 12) v = Tm [nb*3 + (q-9)];
        else if (q < 14) v = fm [nb*2 + (q-12)];
        else if (q < 16) v = cm [nb*2 + (q-14)];
        else if (q < 19) v = km [nb*3 + (q-16)];
        else if (q < 21) v = pm [nb*2 + (q-19)];
        else             v = whm[nb*2 + (q-21)];
        s[i] = v;
    }
    __syncthreads();

    // Voxel coordinates: m = (ix*CY + iy)*CZ + iz
    const int ixg = m / (CY * CZ);
    const int iyg = (m / CZ) % CY;
    const int izg = m % CZ;
    const float gs0 = gs[0], gs1 = gs[1], gs2 = gs[2];
    const float gx = -0.5f*gs0 + (float)ixg * (gs0 / (float)(CX-1)) + gc[b*3+0];
    const float gy = -0.5f*gs1 + (float)iyg * (gs1 / (float)(CY-1)) + gc[b*3+1];
    const float gz = -0.5f*gs2 + (float)izg * (gs2 / (float)(CZ-1)) + gc[b*3+2];

    grids[((long)b*NBINS + m)*3 + 0] = gx;
    grids[((long)b*NBINS + m)*3 + 1] = gy;
    grids[((long)b*NBINS + m)*3 + 2] = gz;

    float den = EPSV;
    float2 acc2[8];
    #pragma unroll
    for (int jj = 0; jj < 8; jj++) acc2[jj] = make_float2(0.f, 0.f);

    #pragma unroll
    for (int n = 0; n < N_CAMS; n++) {
        const float* cp = s + n*23;
        const float dx = gx - cp[9], dy = gy - cp[10], dz = gz - cp[11];
        const float xc0 = cp[0]*dx + cp[1]*dy + cp[2]*dz;
        const float xc1 = cp[3]*dx + cp[4]*dy + cp[5]*dz;
        const float xc2 = cp[6]*dx + cp[7]*dy + cp[8]*dz;
        const float inv = 1.0f / xc2;
        const float y0 = xc0 * inv, y1 = xc1 * inv;
        const float r2 = y0*y0 + y1*y1;
        const float radial = 1.0f + cp[16]*r2 + cp[17]*r2*r2 + cp[18]*r2*r2*r2;
        const float tanp = cp[19]*y1 + cp[20]*y0;
        const float rt = radial + tanp;
        const float xy0 = y0*rt + r2*cp[20];
        const float xy1 = y1*rt + r2*cp[19];
        const float px = xy0*cp[12] + cp[14];
        const float py = xy1*cp[13] + cp[15];
        const float wv = cp[21], hv = cp[22];
        const float bound = (px >= 0.0f && py >= 0.0f && px < wv && py < hv) ? 1.0f : 0.0f;
        den += bound;

        // Warp-uniform skip: bound depends (almost) only on (x,y) of the voxel
        // column, so whole warps agree; when no lane is in-frame, the 8 loads
        // and the combine contribute exactly zero and can be elided.
        const unsigned any_mask = __ballot_sync(0xFFFFFFFFu, bound != 0.0f);
        if (any_mask == 0u) continue;

        const float mwh = fmaxf(wv, hv);
        float pxc = fminf(fmaxf(px, -1.0f), mwh);
        float pyc = fminf(fmaxf(py, -1.0f), mwh);
        float nx = pxc / (wv - 1.0f) * 2.0f - 1.0f;
        float ny = pyc / (hv - 1.0f) * 2.0f - 1.0f;
        nx = fminf(fmaxf(nx, -1.1f), 1.1f);
        ny = fminf(fmaxf(ny, -1.1f), 1.1f);
        const float fx = (nx + 1.0f) * 0.5f * (float)(Wn - 1);
        const float fy = (ny + 1.0f) * 0.5f * (float)(Hn - 1);
        const float x0f = floorf(fx), y0f = floorf(fy);
        const float wx1 = fx - x0f, wx0 = 1.0f - wx1;
        const float wy1 = fy - y0f, wy0 = 1.0f - wy1;
        const int x0i = (int)x0f;
        const int y0i = (int)y0f;
        // Map logical corner weights onto the fetched 2x2 slots (base clamped to [0,W-2]/[0,H-2]).
        // Under bound=1: x0i in [0,W-1], y0i in [0,H-1]. x0i==W-1 => x0 value sits in slot B; x1 invalid.
        const bool xe = (x0i >= Wn-1);
        const bool ye = (y0i >= Hn-1);
        const int xb = min(max(x0i, 0), Wn-2);
        const int yb = min(max(y0i, 0), Hn-2);
        const float wxA = xe ? 0.0f : wx0;
        const float wxB = xe ? wx0  : wx1;
        const float wyA = ye ? 0.0f : wy0;
        const float wyB = ye ? wy0  : wy1;
        const float w00 = wxA*wyA*bound;
        const float w01 = wxB*wyA*bound;
        const float w10 = wxA*wyB*bound;
        const float w11 = wxB*wyB*bound;

        const size_t pixoff = (size_t)yb*Wn + xb;
        const size_t base0 = ((size_t)(n*Bn + b) * 2 * HW + pixoff) * 8;        // chunk0, halves
        const size_t base1 = base0 + (size_t)HW * 8;                            // chunk1

        #pragma unroll
        for (int c = 0; c < 2; c++) {
            const size_t p = c ? base1 : base0;
            const uint4* q0 = reinterpret_cast<const uint4*>(g_packT + p);                    // row yb
            const uint4* q1 = reinterpret_cast<const uint4*>(g_packT + p + (size_t)Wn*8);     // row yb+1
            const uint4 r00 = __ldg(q0);       // pixel (yb,  xb)
            const uint4 r01 = __ldg(q0 + 1);   // pixel (yb,  xb+1)
            const uint4 r10 = __ldg(q1);       // pixel (yb+1,xb)
            const uint4 r11 = __ldg(q1 + 1);   // pixel (yb+1,xb+1)
            const unsigned int* c00 = &r00.x;
            const unsigned int* c01 = &r01.x;
            const unsigned int* c10 = &r10.x;
            const unsigned int* c11 = &r11.x;
            #pragma unroll
            for (int t = 0; t < 4; t++) {
                const int jj = c*4 + t;
                const float2 v00 = __half22float2(*reinterpret_cast<const __half2*>(&c00[t]));
                const float2 v01 = __half22float2(*reinterpret_cast<const __half2*>(&c01[t]));
                const float2 v10 = __half22float2(*reinterpret_cast<const __half2*>(&c10[t]));
                const float2 v11 = __half22float2(*reinterpret_cast<const __half2*>(&c11[t]));
                acc2[jj].x += w00*v00.x + w01*v01.x + w10*v10.x + w11*v11.x;
                acc2[jj].y += w00*v00.y + w01*v01.y + w10*v10.y + w11*v11.y;
            }
        }
    }

    const float invden = 1.0f / den;

    #pragma unroll
    for (int j = 0; j < Jn; j++) {
        const float a = (j & 1) ? acc2[j>>1].y : acc2[j>>1].x;
        float v = a * invden;
        v = fminf(fmaxf(v, 0.0f), 1.0f);
        cubes[((long)b*Jn + j)*NBINS + m] = v;
    }
}

extern "C" void kernel_launch(void* const* d_in, const int* in_sizes, int n_in,
                              void* d_out, int out_size) {
    const float* heat = (const float*)d_in[0];
    const float* Rm   = (const float*)d_in[1];
    const float* Tm   = (const float*)d_in[2];
    const float* fm   = (const float*)d_in[3];
    const float* cm   = (const float*)d_in[4];
    const float* km   = (const float*)d_in[5];
    const float* pm   = (const float*)d_in[6];
    const float* whm  = (const float*)d_in[7];
    const float* gc   = (const float*)d_in[8];
    const float* gs   = (const float*)d_in[9];

    float* cubes = (float*)d_out;
    float* grids = cubes + (long)Bn * Jn * NBINS;   // tuple output: cubes then grids

    pack_kernel<<<(NB * HW) / 256, 256>>>(heat);
    project_kernel<<<Bn * BLOCKS_PER_B, THREADS>>>(Rm, Tm, fm, cm, km, pm, whm, gc, gs,
                                                   cubes, grids);
}

// round 16
// speedup vs baseline: 1.1660x; 1.0562x over previous
#include <cuda_runtime.h>
#include <cuda_fp16.h>
#include <math.h>

#define N_CAMS 5
#define Bn 4
#define Jn 15
#define Hn 128
#define Wn 240
#define CX 80
#define CY 80
#define CZ 20
#define NBINS (CX*CY*CZ)        // 128000
#define HW (Hn*Wn)              // 30720
#define NB (N_CAMS*Bn)          // 20 planes
#define THREADS 256
#define BLOCKS_PER_B (NBINS/THREADS)  // 500
#define EPSV 1e-6f

// Joint-chunked fp16 heatmaps, 4x2-tiled pixel order:
//   record per (cam,b,chunk,pixel) = 8 halves = 16B.
//   pixel order: 4x2 tiles -> one 128B cache line = 4 px (x) * 2 px (y).
// Layout: [nb][chunk][tiled pixel][8]
__device__ __align__(16) __half g_packT[(size_t)NB * 2 * HW * 8 + 64];   // ~19.7 MB

// tiled record index of pixel (y, x)
__host__ __device__ __forceinline__ unsigned int swz(int y, int x) {
    return (((unsigned)(y >> 1) * (Wn >> 2) + (unsigned)(x >> 2)) << 3)
         | ((unsigned)(y & 1) << 2) | (unsigned)(x & 3);
}

__global__ __launch_bounds__(256) void pack_kernel(const float* __restrict__ heat) {
    const int i = blockIdx.x * 256 + threadIdx.x;     // < NB*HW
    const int nb = i / HW;
    const int r  = i - nb * HW;
    const int y  = r / Wn;
    const int x  = r - y * Wn;
    const float* hp = heat + ((size_t)nb * Jn) * HW + r;
    __align__(16) __half tmp[16];
    #pragma unroll
    for (int j = 0; j < Jn; j++)
        tmp[j] = __float2half_rn(hp[(size_t)j * HW]);   // coalesced across warp per j
    tmp[15] = __float2half_rn(0.0f);
    const uint4* src = reinterpret_cast<const uint4*>(tmp);
    const unsigned int t = swz(y, x);
    uint4* base = reinterpret_cast<uint4*>(g_packT);
    base[(size_t)(nb * 2    ) * HW + t] = src[0];
    base[(size_t)(nb * 2 + 1) * HW + t] = src[1];
}

__global__ __launch_bounds__(THREADS) void project_kernel(
    const float* __restrict__ Rm,     // (5,4,3,3)
    const float* __restrict__ Tm,     // (5,4,3)
    const float* __restrict__ fm,     // (5,4,2)
    const float* __restrict__ cm,     // (5,4,2)
    const float* __restrict__ km,     // (5,4,3)
    const float* __restrict__ pm,     // (5,4,2)
    const float* __restrict__ whm,    // (5,4,2)
    const float* __restrict__ gc,     // (4,3)
    const float* __restrict__ gs,     // (3,)
    float* __restrict__ cubes,        // (4,15,128000)
    float* __restrict__ grids)        // (4,128000,3)
{
    __shared__ float s[N_CAMS * 23];

    const int b = blockIdx.x / BLOCKS_PER_B;
    const int m = (blockIdx.x % BLOCKS_PER_B) * THREADS + threadIdx.x;

    // Stage camera params for this batch into shared: per cam 23 floats:
    // R[0..8], T[9..11], f[12..13], c[14..15], k[16..18], p[19..20], wh[21..22]
    for (int i = threadIdx.x; i < N_CAMS * 23; i += THREADS) {
        const int n = i / 23, q = i % 23;
        const int nb = n * Bn + b;
        float v;
        if      (q < 9)  v = Rm [nb*9 + q];
        else if (q < 12) v = Tm [nb*3 + (q-9)];
        else if (q < 14) v = fm [nb*2 + (q-12)];
        else if (q < 16) v = cm [nb*2 + (q-14)];
        else if (q < 19) v = km [nb*3 + (q-16)];
        else if (q < 21) v = pm [nb*2 + (q-19)];
        else             v = whm[nb*2 + (q-21)];
        s[i] = v;
    }
    __syncthreads();

    // Voxel coordinates: m = (ix*CY + iy)*CZ + iz
    const int ixg = m / (CY * CZ);
    const int iyg = (m / CZ) % CY;
    const int izg = m % CZ;
    const float gs0 = gs[0], gs1 = gs[1], gs2 = gs[2];
    const float gx = -0.5f*gs0 + (float)ixg * (gs0 / (float)(CX-1)) + gc[b*3+0];
    const float gy = -0.5f*gs1 + (float)iyg * (gs1 / (float)(CY-1)) + gc[b*3+1];
    const float gz = -0.5f*gs2 + (float)izg * (gs2 / (float)(CZ-1)) + gc[b*3+2];

    grids[((long)b*NBINS + m)*3 + 0] = gx;
    grids[((long)b*NBINS + m)*3 + 1] = gy;
    grids[((long)b*NBINS + m)*3 + 2] = gz;

    float den = EPSV;
    float2 acc2[8];
    #pragma unroll
    for (int jj = 0; jj < 8; jj++) acc2[jj] = make_float2(0.f, 0.f);

    const uint4* __restrict__ P = reinterpret_cast<const uint4*>(g_packT);

    #pragma unroll
    for (int n = 0; n < N_CAMS; n++) {
        const float* cp = s + n*23;
        const float dx = gx - cp[9], dy = gy - cp[10], dz = gz - cp[11];
        const float xc0 = cp[0]*dx + cp[1]*dy + cp[2]*dz;
        const float xc1 = cp[3]*dx + cp[4]*dy + cp[5]*dz;
        const float xc2 = cp[6]*dx + cp[7]*dy + cp[8]*dz;
        const float inv = 1.0f / xc2;
        const float y0 = xc0 * inv, y1 = xc1 * inv;
        const float r2 = y0*y0 + y1*y1;
        const float radial = 1.0f + cp[16]*r2 + cp[17]*r2*r2 + cp[18]*r2*r2*r2;
        const float tanp = cp[19]*y1 + cp[20]*y0;
        const float rt = radial + tanp;
        const float xy0 = y0*rt + r2*cp[20];
        const float xy1 = y1*rt + r2*cp[19];
        const float px = xy0*cp[12] + cp[14];
        const float py = xy1*cp[13] + cp[15];
        const float wv = cp[21], hv = cp[22];
        const float bound = (px >= 0.0f && py >= 0.0f && px < wv && py < hv) ? 1.0f : 0.0f;
        den += bound;

        // Warp-uniform skip: when no lane is in-frame the whole contribution is 0.
        const unsigned any_mask = __ballot_sync(0xFFFFFFFFu, bound != 0.0f);
        if (any_mask == 0u) continue;

        const float mwh = fmaxf(wv, hv);
        float pxc = fminf(fmaxf(px, -1.0f), mwh);
        float pyc = fminf(fmaxf(py, -1.0f), mwh);
        float nx = pxc / (wv - 1.0f) * 2.0f - 1.0f;
        float ny = pyc / (hv - 1.0f) * 2.0f - 1.0f;
        nx = fminf(fmaxf(nx, -1.1f), 1.1f);
        ny = fminf(fmaxf(ny, -1.1f), 1.1f);
        const float fx = (nx + 1.0f) * 0.5f * (float)(Wn - 1);
        const float fy = (ny + 1.0f) * 0.5f * (float)(Hn - 1);
        const float x0f = floorf(fx), y0f = floorf(fy);
        const float wx1 = fx - x0f, wx0 = 1.0f - wx1;
        const float wy1 = fy - y0f, wy0 = 1.0f - wy1;
        const int x0i = (int)x0f;
        const int y0i = (int)y0f;
        // Map logical corner weights onto the fetched 2x2 slots (base clamped to [0,W-2]/[0,H-2]).
        // Under bound=1: x0i in [0,W-1], y0i in [0,H-1]. x0i==W-1 => x0 value sits in slot B; x1 invalid.
        const bool xe = (x0i >= Wn-1);
        const bool ye = (y0i >= Hn-1);
        const int xb = min(max(x0i, 0), Wn-2);
        const int yb = min(max(y0i, 0), Hn-2);
        const float wxA = xe ? 0.0f : wx0;
        const float wxB = xe ? wx0  : wx1;
        const float wyA = ye ? 0.0f : wy0;
        const float wyB = ye ? wy0  : wy1;
        const float w00 = wxA*wyA*bound;
        const float w01 = wxB*wyA*bound;
        const float w10 = wxA*wyB*bound;
        const float w11 = wxB*wyB*bound;

        // Tiled record indices of the 2x2 patch (32-bit arithmetic).
        const unsigned int i00 = swz(yb,     xb);
        const unsigned int i01 = swz(yb,     xb + 1);
        const unsigned int i10 = swz(yb + 1, xb);
        const unsigned int i11 = swz(yb + 1, xb + 1);
        const unsigned int cam0 = (unsigned)(n*Bn + b) * 2u * HW;    // chunk0 plane (records)
        const unsigned int cam1 = cam0 + HW;                          // chunk1 plane

        #pragma unroll
        for (int c = 0; c < 2; c++) {
            const unsigned int base = c ? cam1 : cam0;
            const uint4 r00 = __ldg(P + base + i00);
            const uint4 r01 = __ldg(P + base + i01);
            const uint4 r10 = __ldg(P + base + i10);
            const uint4 r11 = __ldg(P + base + i11);
            const unsigned int* c00 = &r00.x;
            const unsigned int* c01 = &r01.x;
            const unsigned int* c10 = &r10.x;
            const unsigned int* c11 = &r11.x;
            #pragma unroll
            for (int t = 0; t < 4; t++) {
                const int jj = c*4 + t;
                const float2 v00 = __half22float2(*reinterpret_cast<const __half2*>(&c00[t]));
                const float2 v01 = __half22float2(*reinterpret_cast<const __half2*>(&c01[t]));
                const float2 v10 = __half22float2(*reinterpret_cast<const __half2*>(&c10[t]));
                const float2 v11 = __half22float2(*reinterpret_cast<const __half2*>(&c11[t]));
                acc2[jj].x += w00*v00.x + w01*v01.x + w10*v10.x + w11*v11.x;
                acc2[jj].y += w00*v00.y + w01*v01.y + w10*v10.y + w11*v11.y;
            }
        }
    }

    const float invden = 1.0f / den;

    #pragma unroll
    for (int j = 0; j < Jn; j++) {
        const float a = (j & 1) ? acc2[j>>1].y : acc2[j>>1].x;
        float v = a * invden;
        v = fminf(fmaxf(v, 0.0f), 1.0f);
        cubes[((long)b*Jn + j)*NBINS + m] = v;
    }
}

extern "C" void kernel_launch(void* const* d_in, const int* in_sizes, int n_in,
                              void* d_out, int out_size) {
    const float* heat = (const float*)d_in[0];
    const float* Rm   = (const float*)d_in[1];
    const float* Tm   = (const float*)d_in[2];
    const float* fm   = (const float*)d_in[3];
    const float* cm   = (const float*)d_in[4];
    const float* km   = (const float*)d_in[5];
    const float* pm   = (const float*)d_in[6];
    const float* whm  = (const float*)d_in[7];
    const float* gc   = (const float*)d_in[8];
    const float* gs   = (const float*)d_in[9];

    float* cubes = (float*)d_out;
    float* grids = cubes + (long)Bn * Jn * NBINS;   // tuple output: cubes then grids

    pack_kernel<<<(NB * HW) / 256, 256>>>(heat);
    project_kernel<<<Bn * BLOCKS_PER_B, THREADS>>>(Rm, Tm, fm, cm, km, pm, whm, gc, gs,
                                                   cubes, grids);
}

// round 17
// speedup vs baseline: 1.1692x; 1.0027x over previous
#include <cuda_runtime.h>
#include <cuda_fp16.h>
#include <math.h>

#define N_CAMS 5
#define Bn 4
#define Jn 15
#define Hn 128
#define Wn 240
#define CX 80
#define CY 80
#define CZ 20
#define NBINS (CX*CY*CZ)        // 128000
#define HW (Hn*Wn)              // 30720
#define NB (N_CAMS*Bn)          // 20 planes
#define THREADS 256
#define BLOCKS_PER_B (NBINS/THREADS)  // 500
#define EPSV 1e-6f

// Joint-chunked fp16 heatmaps, 4x2-tiled pixel order:
//   record per (cam,b,chunk,pixel) = 8 halves = 16B.
//   pixel order: 4x2 tiles -> one 128B cache line = 4 px (x) * 2 px (y).
// Layout: [nb][chunk][tiled pixel][8]
__device__ __align__(16) __half g_packT[(size_t)NB * 2 * HW * 8 + 64];   // ~19.7 MB

// tiled record index of pixel (y, x)
__host__ __device__ __forceinline__ unsigned int swz(int y, int x) {
    return (((unsigned)(y >> 1) * (Wn >> 2) + (unsigned)(x >> 2)) << 3)
         | ((unsigned)(y & 1) << 2) | (unsigned)(x & 3);
}

__global__ __launch_bounds__(256) void pack_kernel(const float* __restrict__ heat) {
    const int i = blockIdx.x * 256 + threadIdx.x;     // < NB*HW
    const int nb = i / HW;
    const int r  = i - nb * HW;
    const int y  = r / Wn;
    const int x  = r - y * Wn;
    const float* hp = heat + ((size_t)nb * Jn) * HW + r;
    __align__(16) __half tmp[16];
    #pragma unroll
    for (int j = 0; j < Jn; j++)
        tmp[j] = __float2half_rn(hp[(size_t)j * HW]);   // coalesced across warp per j
    tmp[15] = __float2half_rn(0.0f);
    const uint4* src = reinterpret_cast<const uint4*>(tmp);
    const unsigned int t = swz(y, x);
    uint4* base = reinterpret_cast<uint4*>(g_packT);
    base[(size_t)(nb * 2    ) * HW + t] = src[0];
    base[(size_t)(nb * 2 + 1) * HW + t] = src[1];
}

__global__ __launch_bounds__(THREADS) void project_kernel(
    const float* __restrict__ Rm,     // (5,4,3,3)
    const float* __restrict__ Tm,     // (5,4,3)
    const float* __restrict__ fm,     // (5,4,2)
    const float* __restrict__ cm,     // (5,4,2)
    const float* __restrict__ km,     // (5,4,3)
    const float* __restrict__ pm,     // (5,4,2)
    const float* __restrict__ whm,    // (5,4,2)
    const float* __restrict__ gc,     // (4,3)
    const float* __restrict__ gs,     // (3,)
    float* __restrict__ cubes,        // (4,15,128000)
    float* __restrict__ grids)        // (4,128000,3)
{
    __shared__ float s[N_CAMS * 23];

    const int b = blockIdx.x / BLOCKS_PER_B;
    const int m = (blockIdx.x % BLOCKS_PER_B) * THREADS + threadIdx.x;

    // Stage camera params for this batch into shared: per cam 23 floats:
    // R[0..8], T[9..11], f[12..13], c[14..15], k[16..18], p[19..20], wh[21..22]
    for (int i = threadIdx.x; i < N_CAMS * 23; i += THREADS) {
        const int n = i / 23, q = i % 23;
        const int nb = n * Bn + b;
        float v;
        if      (q < 9)  v = Rm [nb*9 + q];
        else if (q < 12) v = Tm [nb*3 + (q-9)];
        else if (q < 14) v = fm [nb*2 + (q-12)];
        else if (q < 16) v = cm [nb*2 + (q-14)];
        else if (q < 19) v = km [nb*3 + (q-16)];
        else if (q < 21) v = pm [nb*2 + (q-19)];
        else             v = whm[nb*2 + (q-21)];
        s[i] = v;
    }
    __syncthreads();

    // Voxel coordinates: m = (ix*CY + iy)*CZ + iz
    const int ixg = m / (CY * CZ);
    const int iyg = (m / CZ) % CY;
    const int izg = m % CZ;
    const float gs0 = gs[0], gs1 = gs[1], gs2 = gs[2];
    const float gx = -0.5f*gs0 + (float)ixg * (gs0 / (float)(CX-1)) + gc[b*3+0];
    const float gy = -0.5f*gs1 + (float)iyg * (gs1 / (float)(CY-1)) + gc[b*3+1];
    const float gz = -0.5f*gs2 + (float)izg * (gs2 / (float)(CZ-1)) + gc[b*3+2];

    grids[((long)b*NBINS + m)*3 + 0] = gx;
    grids[((long)b*NBINS + m)*3 + 1] = gy;
    grids[((long)b*NBINS + m)*3 + 2] = gz;

    float den = EPSV;
    float2 acc2[8];
    #pragma unroll
    for (int jj = 0; jj < 8; jj++) acc2[jj] = make_float2(0.f, 0.f);

    const uint4* __restrict__ P = reinterpret_cast<const uint4*>(g_packT);

    #pragma unroll
    for (int n = 0; n < N_CAMS; n++) {
        const float* cp = s + n*23;
        const float dx = gx - cp[9], dy = gy - cp[10], dz = gz - cp[11];
        const float xc0 = cp[0]*dx + cp[1]*dy + cp[2]*dz;
        const float xc1 = cp[3]*dx + cp[4]*dy + cp[5]*dz;
        const float xc2 = cp[6]*dx + cp[7]*dy + cp[8]*dz;
        const float inv = 1.0f / xc2;
        const float y0 = xc0 * inv, y1 = xc1 * inv;
        const float r2 = y0*y0 + y1*y1;
        const float radial = 1.0f + cp[16]*r2 + cp[17]*r2*r2 + cp[18]*r2*r2*r2;
        const float tanp = cp[19]*y1 + cp[20]*y0;
        const float rt = radial + tanp;
        const float xy0 = y0*rt + r2*cp[20];
        const float xy1 = y1*rt + r2*cp[19];
        const float px = xy0*cp[12] + cp[14];
        const float py = xy1*cp[13] + cp[15];
        const float wv = cp[21], hv = cp[22];
        const float bound = (px >= 0.0f && py >= 0.0f && px < wv && py < hv) ? 1.0f : 0.0f;
        den += bound;

        // Warp-uniform skip: when no lane is in-frame the whole contribution is 0.
        const unsigned any_mask = __ballot_sync(0xFFFFFFFFu, bound != 0.0f);
        if (any_mask == 0u) continue;

        const float mwh = fmaxf(wv, hv);
        float pxc = fminf(fmaxf(px, -1.0f), mwh);
        float pyc = fminf(fmaxf(py, -1.0f), mwh);
        float nx = pxc / (wv - 1.0f) * 2.0f - 1.0f;
        float ny = pyc / (hv - 1.0f) * 2.0f - 1.0f;
        nx = fminf(fmaxf(nx, -1.1f), 1.1f);
        ny = fminf(fmaxf(ny, -1.1f), 1.1f);
        const float fx = (nx + 1.0f) * 0.5f * (float)(Wn - 1);
        const float fy = (ny + 1.0f) * 0.5f * (float)(Hn - 1);
        const float x0f = floorf(fx), y0f = floorf(fy);
        const float wx1 = fx - x0f, wx0 = 1.0f - wx1;
        const float wy1 = fy - y0f, wy0 = 1.0f - wy1;
        const int x0i = (int)x0f;
        const int y0i = (int)y0f;
        // Map logical corner weights onto the fetched 2x2 slots (base clamped to [0,W-2]/[0,H-2]).
        // Under bound=1: x0i in [0,W-1], y0i in [0,H-1]. x0i==W-1 => x0 value sits in slot B; x1 invalid.
        const bool xe = (x0i >= Wn-1);
        const bool ye = (y0i >= Hn-1);
        const int xb = min(max(x0i, 0), Wn-2);
        const int yb = min(max(y0i, 0), Hn-2);
        const float wxA = xe ? 0.0f : wx0;
        const float wxB = xe ? wx0  : wx1;
        const float wyA = ye ? 0.0f : wy0;
        const float wyB = ye ? wy0  : wy1;
        // y-weights carry bound; x-weights go to fp16 broadcast for the packed x-lerp.
        const float wyAb = wyA * bound;
        const float wyBb = wyB * bound;
        const __half2 hwxA = __float2half2_rn(wxA);
        const __half2 hwxB = __float2half2_rn(wxB);

        // Tiled record indices of the 2x2 patch via incremental deltas:
        //   x+1: +1 inside a tile, +5 when crossing a tile boundary (x&3 == 3)
        //   y+1: +4 inside a tile, +476 when crossing (y&1 == 1): 60 tiles * 8 - 4
        const unsigned int i00 = swz(yb, xb);
        const unsigned int dxs = ((xb & 3) == 3) ? 5u : 1u;
        const unsigned int dys = (yb & 1) ? 476u : 4u;
        const unsigned int i01 = i00 + dxs;
        const unsigned int i10 = i00 + dys;
        const unsigned int i11 = i10 + dxs;
        const unsigned int cam0 = (unsigned)(n*Bn + b) * 2u * HW;    // chunk0 plane (records)
        const unsigned int cam1 = cam0 + HW;                          // chunk1 plane

        #pragma unroll
        for (int c = 0; c < 2; c++) {
            const unsigned int base = c ? cam1 : cam0;
            const uint4 r00 = __ldg(P + base + i00);
            const uint4 r01 = __ldg(P + base + i01);
            const uint4 r10 = __ldg(P + base + i10);
            const uint4 r11 = __ldg(P + base + i11);
            const unsigned int* c00 = &r00.x;
            const unsigned int* c01 = &r01.x;
            const unsigned int* c10 = &r10.x;
            const unsigned int* c11 = &r11.x;
            #pragma unroll
            for (int t = 0; t < 4; t++) {
                const int jj = c*4 + t;
                const __half2 v00 = *reinterpret_cast<const __half2*>(&c00[t]);
                const __half2 v01 = *reinterpret_cast<const __half2*>(&c01[t]);
                const __half2 v10 = *reinterpret_cast<const __half2*>(&c10[t]);
                const __half2 v11 = *reinterpret_cast<const __half2*>(&c11[t]);
                // Shallow fp16 x-lerp (depth 2, independent per slot)
                const __half2 rx0 = __hfma2(v01, hwxB, __hmul2(v00, hwxA));
                const __half2 rx1 = __hfma2(v11, hwxB, __hmul2(v10, hwxA));
                const float2 f0 = __half22float2(rx0);
                const float2 f1 = __half22float2(rx1);
                // fp32 y-combine + accumulate
                acc2[jj].x += wyAb*f0.x + wyBb*f1.x;
                acc2[jj].y += wyAb*f0.y + wyBb*f1.y;
            }
        }
    }

    const float invden = 1.0f / den;

    #pragma unroll
    for (int j = 0; j < Jn; j++) {
        const float a = (j & 1) ? acc2[j>>1].y : acc2[j>>1].x;
        float v = a * invden;
        v = fminf(fmaxf(v, 0.0f), 1.0f);
        cubes[((long)b*Jn + j)*NBINS + m] = v;
    }
}

extern "C" void kernel_launch(void* const* d_in, const int* in_sizes, int n_in,
                              void* d_out, int out_size) {
    const float* heat = (const float*)d_in[0];
    const float* Rm   = (const float*)d_in[1];
    const float* Tm   = (const float*)d_in[2];
    const float* fm   = (const float*)d_in[3];
    const float* cm   = (const float*)d_in[4];
    const float* km   = (const float*)d_in[5];
    const float* pm   = (const float*)d_in[6];
    const float* whm  = (const float*)d_in[7];
    const float* gc   = (const float*)d_in[8];
    const float* gs   = (const float*)d_in[9];

    float* cubes = (float*)d_out;
    float* grids = cubes + (long)Bn * Jn * NBINS;   // tuple output: cubes then grids

    pack_kernel<<<(NB * HW) / 256, 256>>>(heat);
    project_kernel<<<Bn * BLOCKS_PER_B, THREADS>>>(Rm, Tm, fm, cm, km, pm, whm, gc, gs,
                                                   cubes, grids);
}